// round 1
// baseline (speedup 1.0000x reference)
#include <cuda_runtime.h>
#include <math.h>

// Problem constants (fixed shapes per reference):
//   x  [2,2048,1024] f32   -> T=4096 tokens, E=1024
//   Wr [1024,8] f32, br [8] f32
//   W1 [8,1024,4096] f32, b1 [8,4096] f32
//   W2 [8,4096,1024] f32, b2 [8,1024] f32
//   top_k = 2
#define TNUM 4096
#define EDIM 1024
#define NEXP 8
#define HDIM 4096
#define CAP  4096   // worst case: every token routes to one expert

// Scratch (device globals: allocation-free per harness rules)
__device__ float g_hid[(size_t)NEXP * CAP * HDIM];  // 512 MB, only count[e] rows used
__device__ int   g_cnt[NEXP];
__device__ int   g_tok[NEXP * CAP];
__device__ float g_wgt[NEXP * CAP];

__device__ __forceinline__ float gelu_exact(float v) {
    return 0.5f * v * (1.0f + erff(v * 0.70710678118654752f));
}

// ---------------------------------------------------------------------------
// K0: zero output + expert counters
// ---------------------------------------------------------------------------
__global__ void k_zero(float* __restrict__ out) {
    size_t i = (size_t)blockIdx.x * blockDim.x + threadIdx.x;
    size_t n4 = (size_t)TNUM * EDIM / 4;
    if (i < n4) ((float4*)out)[i] = make_float4(0.f, 0.f, 0.f, 0.f);
    if (blockIdx.x == 0 && threadIdx.x < NEXP) g_cnt[threadIdx.x] = 0;
}

// ---------------------------------------------------------------------------
// K1: router — warp per token: logits = x@Wr + br, top-2, 2-way softmax,
// atomic slot assignment into per-expert compact lists.
// ---------------------------------------------------------------------------
__global__ __launch_bounds__(256) void k_router(const float* __restrict__ x,
                                                const float* __restrict__ Wr,
                                                const float* __restrict__ br) {
    int warp = (blockIdx.x * blockDim.x + threadIdx.x) >> 5;
    int lane = threadIdx.x & 31;
    if (warp >= TNUM) return;
    const float* xr = x + (size_t)warp * EDIM;

    float acc[NEXP];
#pragma unroll
    for (int n = 0; n < NEXP; n++) acc[n] = 0.f;

    for (int k = lane; k < EDIM; k += 32) {
        float xv = xr[k];
        const float4* w4 = (const float4*)(Wr + (size_t)k * NEXP);
        float4 a = w4[0], b = w4[1];
        acc[0] += xv * a.x; acc[1] += xv * a.y; acc[2] += xv * a.z; acc[3] += xv * a.w;
        acc[4] += xv * b.x; acc[5] += xv * b.y; acc[6] += xv * b.z; acc[7] += xv * b.w;
    }
#pragma unroll
    for (int n = 0; n < NEXP; n++) {
#pragma unroll
        for (int o = 16; o > 0; o >>= 1)
            acc[n] += __shfl_xor_sync(0xffffffffu, acc[n], o);
    }
    if (lane == 0) {
        float l[NEXP];
#pragma unroll
        for (int n = 0; n < NEXP; n++) l[n] = acc[n] + br[n];
        // top-2, stable (lowest index on ties) to match jax.lax.top_k selection set
        int i0 = 0;
#pragma unroll
        for (int n = 1; n < NEXP; n++) if (l[n] > l[i0]) i0 = n;
        int i1 = -1;
#pragma unroll
        for (int n = 0; n < NEXP; n++) {
            if (n == i0) continue;
            if (i1 < 0 || l[n] > l[i1]) i1 = n;
        }
        // softmax over {l[i0], l[i1]}, l[i0] is max
        float d  = __expf(l[i1] - l[i0]);
        float w0 = 1.f / (1.f + d);
        float w1 = d * w0;
        int s0 = atomicAdd(&g_cnt[i0], 1);
        g_tok[i0 * CAP + s0] = warp;  g_wgt[i0 * CAP + s0] = w0;
        int s1 = atomicAdd(&g_cnt[i1], 1);
        g_tok[i1 * CAP + s1] = warp;  g_wgt[i1 * CAP + s1] = w1;
    }
}

// ---------------------------------------------------------------------------
// K2: grouped SGEMM1 + GELU:  hid[row,:] = gelu(x[tok(row)] @ W1[e] + b1[e])
// Tile 128x128xK16, 256 threads, 8x8 register micro-tile. blockIdx.z = expert
// (expert-major launch order -> per-expert weight reuse caught in L2).
// ---------------------------------------------------------------------------
__global__ __launch_bounds__(256, 2) void k_ffn1(const float* __restrict__ x,
                                                 const float* __restrict__ W1,
                                                 const float* __restrict__ b1) {
    int e   = blockIdx.z;
    int cnt = g_cnt[e];
    int m0  = blockIdx.y * 128;
    if (m0 >= cnt) return;
    int n0  = blockIdx.x * 128;

    __shared__ float As[16][128 + 4];
    __shared__ float Bs[16][128];
    __shared__ int   toks[128];

    int tid = threadIdx.x;
    if (tid < 128) {
        int m = m0 + tid;
        toks[tid] = (m < cnt) ? g_tok[e * CAP + m] : -1;
    }
    __syncthreads();

    const float* Wp = W1 + (size_t)e * EDIM * HDIM + n0;

    float acc[8][8];
#pragma unroll
    for (int i = 0; i < 8; i++)
#pragma unroll
        for (int j = 0; j < 8; j++) acc[i][j] = 0.f;

    int ty = tid >> 4, tx = tid & 15;

    for (int k0 = 0; k0 < EDIM; k0 += 16) {
        // A tile: gathered x rows, stored transposed As[k][m]
#pragma unroll
        for (int i = 0; i < 2; i++) {
            int lin = tid + i * 256;          // 0..511 -> [128 m][4 quad]
            int m = lin >> 2, kq = (lin & 3) * 4;
            int tok = toks[m];
            float4 v = make_float4(0.f, 0.f, 0.f, 0.f);
            if (tok >= 0) v = *(const float4*)(x + (size_t)tok * EDIM + k0 + kq);
            As[kq + 0][m] = v.x; As[kq + 1][m] = v.y;
            As[kq + 2][m] = v.z; As[kq + 3][m] = v.w;
        }
        // B tile: W1[e][k0+kk][n0+nn], contiguous along n
#pragma unroll
        for (int i = 0; i < 2; i++) {
            int lin = tid + i * 256;          // 0..511 -> [16 kk][32 quad]
            int kk = lin >> 5, nq = (lin & 31) * 4;
            *(float4*)&Bs[kk][nq] = *(const float4*)(Wp + (size_t)(k0 + kk) * HDIM + nq);
        }
        __syncthreads();
#pragma unroll
        for (int kk = 0; kk < 16; kk++) {
            float ra[8], rb[8];
#pragma unroll
            for (int i = 0; i < 8; i++) ra[i] = As[kk][ty * 8 + i];
#pragma unroll
            for (int j = 0; j < 8; j++) rb[j] = Bs[kk][tx * 8 + j];
#pragma unroll
            for (int i = 0; i < 8; i++)
#pragma unroll
                for (int j = 0; j < 8; j++) acc[i][j] += ra[i] * rb[j];
        }
        __syncthreads();
    }

    // epilogue: + b1, exact GELU, store hid
    float bb[8];
    const float* bp = b1 + (size_t)e * HDIM + n0 + tx * 8;
#pragma unroll
    for (int j = 0; j < 8; j++) bb[j] = bp[j];

#pragma unroll
    for (int i = 0; i < 8; i++) {
        int m = m0 + ty * 8 + i;
        if (m >= cnt) continue;
        float* hp = g_hid + ((size_t)e * CAP + m) * HDIM + n0 + tx * 8;
#pragma unroll
        for (int j = 0; j < 8; j += 4) {
            float4 v;
            v.x = gelu_exact(acc[i][j + 0] + bb[j + 0]);
            v.y = gelu_exact(acc[i][j + 1] + bb[j + 1]);
            v.z = gelu_exact(acc[i][j + 2] + bb[j + 2]);
            v.w = gelu_exact(acc[i][j + 3] + bb[j + 3]);
            *(float4*)(hp + j) = v;
        }
    }
}

// ---------------------------------------------------------------------------
// K3: grouped SGEMM2 + weighted scatter:
//   out[tok(row),:] += w(row) * (hid[row,:] @ W2[e] + b2[e])
// Exactly 2 commutative atomic adds per output element -> deterministic.
// ---------------------------------------------------------------------------
__global__ __launch_bounds__(256, 2) void k_ffn2(const float* __restrict__ W2,
                                                 const float* __restrict__ b2,
                                                 float* __restrict__ out) {
    int e   = blockIdx.z;
    int cnt = g_cnt[e];
    int m0  = blockIdx.y * 128;
    if (m0 >= cnt) return;
    int n0  = blockIdx.x * 128;

    __shared__ float As[16][128 + 4];
    __shared__ float Bs[16][128];
    __shared__ int   toks[128];
    __shared__ float wts[128];

    int tid = threadIdx.x;
    if (tid < 128) {
        int m = m0 + tid;
        bool v = (m < cnt);
        toks[tid] = v ? g_tok[e * CAP + m] : -1;
        wts[tid]  = v ? g_wgt[e * CAP + m] : 0.f;
    }
    __syncthreads();

    const float* Ap = g_hid + (size_t)(e * CAP + m0) * HDIM;
    const float* Wp = W2 + (size_t)e * HDIM * EDIM + n0;

    float acc[8][8];
#pragma unroll
    for (int i = 0; i < 8; i++)
#pragma unroll
        for (int j = 0; j < 8; j++) acc[i][j] = 0.f;

    int ty = tid >> 4, tx = tid & 15;
    int mlim = cnt - m0;  // valid rows in this tile

    for (int k0 = 0; k0 < HDIM; k0 += 16) {
#pragma unroll
        for (int i = 0; i < 2; i++) {
            int lin = tid + i * 256;
            int m = lin >> 2, kq = (lin & 3) * 4;
            float4 v = make_float4(0.f, 0.f, 0.f, 0.f);
            if (m < mlim) v = *(const float4*)(Ap + (size_t)m * HDIM + k0 + kq);
            As[kq + 0][m] = v.x; As[kq + 1][m] = v.y;
            As[kq + 2][m] = v.z; As[kq + 3][m] = v.w;
        }
#pragma unroll
        for (int i = 0; i < 2; i++) {
            int lin = tid + i * 256;
            int kk = lin >> 5, nq = (lin & 31) * 4;
            *(float4*)&Bs[kk][nq] = *(const float4*)(Wp + (size_t)(k0 + kk) * EDIM + nq);
        }
        __syncthreads();
#pragma unroll
        for (int kk = 0; kk < 16; kk++) {
            float ra[8], rb[8];
#pragma unroll
            for (int i = 0; i < 8; i++) ra[i] = As[kk][ty * 8 + i];
#pragma unroll
            for (int j = 0; j < 8; j++) rb[j] = Bs[kk][tx * 8 + j];
#pragma unroll
            for (int i = 0; i < 8; i++)
#pragma unroll
                for (int j = 0; j < 8; j++) acc[i][j] += ra[i] * rb[j];
        }
        __syncthreads();
    }

    float bb[8];
    const float* bp = b2 + (size_t)e * EDIM + n0 + tx * 8;
#pragma unroll
    for (int j = 0; j < 8; j++) bb[j] = bp[j];

#pragma unroll
    for (int i = 0; i < 8; i++) {
        int ml = ty * 8 + i;
        int tok = toks[ml];
        if (tok < 0) continue;
        float w = wts[ml];
        float* op = out + (size_t)tok * EDIM + n0 + tx * 8;
#pragma unroll
        for (int j = 0; j < 8; j++)
            atomicAdd(op + j, w * (acc[i][j] + bb[j]));
    }
}

// ---------------------------------------------------------------------------
extern "C" void kernel_launch(void* const* d_in, const int* in_sizes, int n_in,
                              void* d_out, int out_size) {
    const float* x  = (const float*)d_in[0];
    const float* Wr = (const float*)d_in[1];
    const float* br = (const float*)d_in[2];
    const float* W1 = (const float*)d_in[3];
    const float* b1 = (const float*)d_in[4];
    const float* W2 = (const float*)d_in[5];
    const float* b2 = (const float*)d_in[6];
    float* out = (float*)d_out;
    (void)in_sizes; (void)n_in; (void)out_size;

    k_zero<<<4096, 256>>>(out);
    k_router<<<TNUM / 8, 256>>>(x, Wr, br);
    dim3 g1(HDIM / 128, CAP / 128, NEXP);   // (32, 32, 8) — most M-tiles early-exit
    k_ffn1<<<g1, 256>>>(x, W1, b1);
    dim3 g2(EDIM / 128, CAP / 128, NEXP);   // (8, 32, 8)
    k_ffn2<<<g2, 256>>>(W2, b2, out);
}

// round 2
// speedup vs baseline: 2.3207x; 2.3207x over previous
#include <cuda_runtime.h>
#include <math.h>

// Shapes: x[2,2048,1024] f32 -> T=4096, E=1024; Wr[1024,8]; W1[8,1024,4096];
// b1[8,4096]; W2[8,4096,1024]; b2[8,1024]; top_k=2.
#define TNUM 4096
#define EDIM 1024
#define NEXP 8
#define HDIM 4096
#define CAP  4096

// Scratch (device globals: allocation-free per harness rules)
__device__ float g_hid[(size_t)NEXP * CAP * HDIM];
__device__ int   g_cnt[NEXP];
__device__ int   g_tok[NEXP * CAP];
__device__ float g_wgt[NEXP * CAP];

__device__ __forceinline__ float gelu_exact(float v) {
    return 0.5f * v * (1.0f + erff(v * 0.70710678118654752f));
}

__device__ __forceinline__ float to_tf32(float v) {
    float r;
    asm("cvt.rna.tf32.f32 %0, %1;" : "=f"(r) : "f"(v));
    return r;
}

__device__ __forceinline__ void mma_tf32(float* c, const unsigned* a, const unsigned* b) {
    asm volatile(
        "mma.sync.aligned.m16n8k8.row.col.f32.tf32.tf32.f32 "
        "{%0,%1,%2,%3}, {%4,%5,%6,%7}, {%8,%9}, {%0,%1,%2,%3};"
        : "+f"(c[0]), "+f"(c[1]), "+f"(c[2]), "+f"(c[3])
        : "r"(a[0]), "r"(a[1]), "r"(a[2]), "r"(a[3]), "r"(b[0]), "r"(b[1]));
}

// ---------------------------------------------------------------------------
// K0: zero output + counters
// ---------------------------------------------------------------------------
__global__ void k_zero(float* __restrict__ out) {
    size_t i = (size_t)blockIdx.x * blockDim.x + threadIdx.x;
    size_t n4 = (size_t)TNUM * EDIM / 4;
    if (i < n4) ((float4*)out)[i] = make_float4(0.f, 0.f, 0.f, 0.f);
    if (blockIdx.x == 0 && threadIdx.x < NEXP) g_cnt[threadIdx.x] = 0;
}

// ---------------------------------------------------------------------------
// K1: router (exact fp32): logits, top-2, 2-way softmax, compact lists
// ---------------------------------------------------------------------------
__global__ __launch_bounds__(256) void k_router(const float* __restrict__ x,
                                                const float* __restrict__ Wr,
                                                const float* __restrict__ br) {
    int warp = (blockIdx.x * blockDim.x + threadIdx.x) >> 5;
    int lane = threadIdx.x & 31;
    if (warp >= TNUM) return;
    const float* xr = x + (size_t)warp * EDIM;

    float acc[NEXP];
#pragma unroll
    for (int n = 0; n < NEXP; n++) acc[n] = 0.f;
    for (int k = lane; k < EDIM; k += 32) {
        float xv = xr[k];
        const float4* w4 = (const float4*)(Wr + (size_t)k * NEXP);
        float4 a = w4[0], b = w4[1];
        acc[0] += xv * a.x; acc[1] += xv * a.y; acc[2] += xv * a.z; acc[3] += xv * a.w;
        acc[4] += xv * b.x; acc[5] += xv * b.y; acc[6] += xv * b.z; acc[7] += xv * b.w;
    }
#pragma unroll
    for (int n = 0; n < NEXP; n++)
#pragma unroll
        for (int o = 16; o > 0; o >>= 1)
            acc[n] += __shfl_xor_sync(0xffffffffu, acc[n], o);
    if (lane == 0) {
        float l[NEXP];
#pragma unroll
        for (int n = 0; n < NEXP; n++) l[n] = acc[n] + br[n];
        int i0 = 0;
#pragma unroll
        for (int n = 1; n < NEXP; n++) if (l[n] > l[i0]) i0 = n;
        int i1 = -1;
#pragma unroll
        for (int n = 0; n < NEXP; n++) {
            if (n == i0) continue;
            if (i1 < 0 || l[n] > l[i1]) i1 = n;
        }
        float d  = __expf(l[i1] - l[i0]);
        float w0 = 1.f / (1.f + d);
        float w1 = d * w0;
        int s0 = atomicAdd(&g_cnt[i0], 1);
        g_tok[i0 * CAP + s0] = warp;  g_wgt[i0 * CAP + s0] = w0;
        int s1 = atomicAdd(&g_cnt[i1], 1);
        g_tok[i1 * CAP + s1] = warp;  g_wgt[i1 * CAP + s1] = w1;
    }
}

// ---------------------------------------------------------------------------
// tf32 tensor-core grouped GEMMs. Tile 128x128xBK16, 256 thr = 8 warps (2x4),
// warp tile 64x32, mma m16n8k8. SMEM pad +8 -> fragment LDS conflict-free.
// ---------------------------------------------------------------------------
#define SPAD 136

// K2: hid = gelu(gather(x) @ W1[e] + b1[e])
__global__ __launch_bounds__(256, 2) void k_ffn1(const float* __restrict__ x,
                                                 const float* __restrict__ W1,
                                                 const float* __restrict__ b1) {
    int e   = blockIdx.z;
    int cnt = g_cnt[e];
    int m0  = blockIdx.y * 128;
    if (m0 >= cnt) return;
    int n0  = blockIdx.x * 128;

    __shared__ float As[16][SPAD];
    __shared__ float Bs[16][SPAD];
    __shared__ int   toks[128];

    int tid = threadIdx.x;
    if (tid < 128) {
        int m = m0 + tid;
        toks[tid] = (m < cnt) ? g_tok[e * CAP + m] : -1;
    }
    __syncthreads();

    const float* Wp = W1 + (size_t)e * EDIM * HDIM + n0;

    int lane = tid & 31, warp = tid >> 5;
    int gi = lane >> 2, qk = lane & 3;
    int wm = (warp >> 2) * 64, wn = (warp & 3) * 32;

    float acc[4][4][4];
#pragma unroll
    for (int i = 0; i < 4; i++)
#pragma unroll
        for (int j = 0; j < 4; j++)
#pragma unroll
            for (int r = 0; r < 4; r++) acc[i][j][r] = 0.f;

    for (int k0 = 0; k0 < EDIM; k0 += 16) {
        // A tile (gathered x rows), transposed As[k][m], tf32-rounded
#pragma unroll
        for (int i = 0; i < 2; i++) {
            int lin = tid + i * 256;
            int m = lin >> 2, kq = (lin & 3) * 4;
            int tok = toks[m];
            float4 v = make_float4(0.f, 0.f, 0.f, 0.f);
            if (tok >= 0) v = *(const float4*)(x + (size_t)tok * EDIM + k0 + kq);
            As[kq + 0][m] = to_tf32(v.x); As[kq + 1][m] = to_tf32(v.y);
            As[kq + 2][m] = to_tf32(v.z); As[kq + 3][m] = to_tf32(v.w);
        }
        // B tile: W1[e][k][n], n contiguous
#pragma unroll
        for (int i = 0; i < 2; i++) {
            int lin = tid + i * 256;
            int kk = lin >> 5, nq = (lin & 31) * 4;
            float4 v = *(const float4*)(Wp + (size_t)(k0 + kk) * HDIM + nq);
            Bs[kk][nq + 0] = to_tf32(v.x); Bs[kk][nq + 1] = to_tf32(v.y);
            Bs[kk][nq + 2] = to_tf32(v.z); Bs[kk][nq + 3] = to_tf32(v.w);
        }
        __syncthreads();

#pragma unroll
        for (int ks = 0; ks < 16; ks += 8) {
            unsigned a[4][4], b[4][2];
#pragma unroll
            for (int mi = 0; mi < 4; mi++) {
                int mb = wm + mi * 16 + gi;
                a[mi][0] = __float_as_uint(As[ks + qk][mb]);
                a[mi][1] = __float_as_uint(As[ks + qk][mb + 8]);
                a[mi][2] = __float_as_uint(As[ks + qk + 4][mb]);
                a[mi][3] = __float_as_uint(As[ks + qk + 4][mb + 8]);
            }
#pragma unroll
            for (int nj = 0; nj < 4; nj++) {
                int nb = wn + nj * 8 + gi;
                b[nj][0] = __float_as_uint(Bs[ks + qk][nb]);
                b[nj][1] = __float_as_uint(Bs[ks + qk + 4][nb]);
            }
#pragma unroll
            for (int mi = 0; mi < 4; mi++)
#pragma unroll
                for (int nj = 0; nj < 4; nj++)
                    mma_tf32(acc[mi][nj], a[mi], b[nj]);
        }
        __syncthreads();
    }

    // epilogue: +b1, exact GELU, store hid
#pragma unroll
    for (int nj = 0; nj < 4; nj++) {
        int n = n0 + wn + nj * 8 + qk * 2;
        float b1a = b1[(size_t)e * HDIM + n];
        float b1b = b1[(size_t)e * HDIM + n + 1];
#pragma unroll
        for (int mi = 0; mi < 4; mi++) {
#pragma unroll
            for (int h = 0; h < 2; h++) {
                int m = m0 + wm + mi * 16 + gi + h * 8;
                if (m >= cnt) continue;
                float2 v;
                v.x = gelu_exact(acc[mi][nj][h * 2 + 0] + b1a);
                v.y = gelu_exact(acc[mi][nj][h * 2 + 1] + b1b);
                *(float2*)(g_hid + ((size_t)e * CAP + m) * HDIM + n) = v;
            }
        }
    }
}

// K3: out[tok] += w * (hid @ W2[e] + b2[e])
__global__ __launch_bounds__(256, 2) void k_ffn2(const float* __restrict__ W2,
                                                 const float* __restrict__ b2,
                                                 float* __restrict__ out) {
    int e   = blockIdx.z;
    int cnt = g_cnt[e];
    int m0  = blockIdx.y * 128;
    if (m0 >= cnt) return;
    int n0  = blockIdx.x * 128;

    __shared__ float As[16][SPAD];
    __shared__ float Bs[16][SPAD];
    __shared__ int   toks[128];
    __shared__ float wts[128];

    int tid = threadIdx.x;
    if (tid < 128) {
        int m = m0 + tid;
        bool v = (m < cnt);
        toks[tid] = v ? g_tok[e * CAP + m] : -1;
        wts[tid]  = v ? g_wgt[e * CAP + m] : 0.f;
    }
    __syncthreads();

    const float* Ap = g_hid + (size_t)(e * CAP + m0) * HDIM;
    const float* Wp = W2 + (size_t)e * HDIM * EDIM + n0;
    int mlim = cnt - m0;

    int lane = tid & 31, warp = tid >> 5;
    int gi = lane >> 2, qk = lane & 3;
    int wm = (warp >> 2) * 64, wn = (warp & 3) * 32;

    float acc[4][4][4];
#pragma unroll
    for (int i = 0; i < 4; i++)
#pragma unroll
        for (int j = 0; j < 4; j++)
#pragma unroll
            for (int r = 0; r < 4; r++) acc[i][j][r] = 0.f;

    for (int k0 = 0; k0 < HDIM; k0 += 16) {
#pragma unroll
        for (int i = 0; i < 2; i++) {
            int lin = tid + i * 256;
            int m = lin >> 2, kq = (lin & 3) * 4;
            float4 v = make_float4(0.f, 0.f, 0.f, 0.f);
            if (m < mlim) v = *(const float4*)(Ap + (size_t)m * HDIM + k0 + kq);
            As[kq + 0][m] = to_tf32(v.x); As[kq + 1][m] = to_tf32(v.y);
            As[kq + 2][m] = to_tf32(v.z); As[kq + 3][m] = to_tf32(v.w);
        }
#pragma unroll
        for (int i = 0; i < 2; i++) {
            int lin = tid + i * 256;
            int kk = lin >> 5, nq = (lin & 31) * 4;
            float4 v = *(const float4*)(Wp + (size_t)(k0 + kk) * EDIM + nq);
            Bs[kk][nq + 0] = to_tf32(v.x); Bs[kk][nq + 1] = to_tf32(v.y);
            Bs[kk][nq + 2] = to_tf32(v.z); Bs[kk][nq + 3] = to_tf32(v.w);
        }
        __syncthreads();

#pragma unroll
        for (int ks = 0; ks < 16; ks += 8) {
            unsigned a[4][4], b[4][2];
#pragma unroll
            for (int mi = 0; mi < 4; mi++) {
                int mb = wm + mi * 16 + gi;
                a[mi][0] = __float_as_uint(As[ks + qk][mb]);
                a[mi][1] = __float_as_uint(As[ks + qk][mb + 8]);
                a[mi][2] = __float_as_uint(As[ks + qk + 4][mb]);
                a[mi][3] = __float_as_uint(As[ks + qk + 4][mb + 8]);
            }
#pragma unroll
            for (int nj = 0; nj < 4; nj++) {
                int nb = wn + nj * 8 + gi;
                b[nj][0] = __float_as_uint(Bs[ks + qk][nb]);
                b[nj][1] = __float_as_uint(Bs[ks + qk + 4][nb]);
            }
#pragma unroll
            for (int mi = 0; mi < 4; mi++)
#pragma unroll
                for (int nj = 0; nj < 4; nj++)
                    mma_tf32(acc[mi][nj], a[mi], b[nj]);
        }
        __syncthreads();
    }

#pragma unroll
    for (int nj = 0; nj < 4; nj++) {
        int n = n0 + wn + nj * 8 + qk * 2;
        float b2a = b2[(size_t)e * EDIM + n];
        float b2b = b2[(size_t)e * EDIM + n + 1];
#pragma unroll
        for (int mi = 0; mi < 4; mi++) {
#pragma unroll
            for (int h = 0; h < 2; h++) {
                int ml = wm + mi * 16 + gi + h * 8;
                int tok = toks[ml];
                if (tok < 0) continue;
                float w = wts[ml];
                float* op = out + (size_t)tok * EDIM + n;
                atomicAdd(op + 0, w * (acc[mi][nj][h * 2 + 0] + b2a));
                atomicAdd(op + 1, w * (acc[mi][nj][h * 2 + 1] + b2b));
            }
        }
    }
}

// ---------------------------------------------------------------------------
extern "C" void kernel_launch(void* const* d_in, const int* in_sizes, int n_in,
                              void* d_out, int out_size) {
    const float* x  = (const float*)d_in[0];
    const float* Wr = (const float*)d_in[1];
    const float* br = (const float*)d_in[2];
    const float* W1 = (const float*)d_in[3];
    const float* b1 = (const float*)d_in[4];
    const float* W2 = (const float*)d_in[5];
    const float* b2 = (const float*)d_in[6];
    float* out = (float*)d_out;
    (void)in_sizes; (void)n_in; (void)out_size;

    k_zero<<<4096, 256>>>(out);
    k_router<<<TNUM / 8, 256>>>(x, Wr, br);
    dim3 g1(HDIM / 128, CAP / 128, NEXP);   // (32, 32, 8), empty M-tiles early-exit
    k_ffn1<<<g1, 256>>>(x, W1, b1);
    dim3 g2(EDIM / 128, CAP / 128, NEXP);   // (8, 32, 8)
    k_ffn2<<<g2, 256>>>(W2, b2, out);
}

// round 3
// speedup vs baseline: 2.3361x; 1.0066x over previous
#include <cuda_runtime.h>
#include <math.h>

// Shapes: x[2,2048,1024] f32 -> T=4096, E=1024; Wr[1024,8]; W1[8,1024,4096];
// b1[8,4096]; W2[8,4096,1024]; b2[8,1024]; top_k=2.
#define TNUM 4096
#define EDIM 1024
#define NEXP 8
#define HDIM 4096
#define CAP  4096

// Scratch (device globals: allocation-free per harness rules)
__device__ float g_hid[(size_t)NEXP * CAP * HDIM];
__device__ int   g_cnt[NEXP];
__device__ int   g_tok[NEXP * CAP];
__device__ float g_wgt[NEXP * CAP];

__device__ __forceinline__ float gelu_exact(float v) {
    return 0.5f * v * (1.0f + erff(v * 0.70710678118654752f));
}

__device__ __forceinline__ float to_tf32(float v) {
    float r;
    asm("cvt.rna.tf32.f32 %0, %1;" : "=f"(r) : "f"(v));
    return r;
}

__device__ __forceinline__ void mma_tf32(float* c, const unsigned* a, const unsigned* b) {
    asm volatile(
        "mma.sync.aligned.m16n8k8.row.col.f32.tf32.tf32.f32 "
        "{%0,%1,%2,%3}, {%4,%5,%6,%7}, {%8,%9}, {%0,%1,%2,%3};"
        : "+f"(c[0]), "+f"(c[1]), "+f"(c[2]), "+f"(c[3])
        : "r"(a[0]), "r"(a[1]), "r"(a[2]), "r"(a[3]), "r"(b[0]), "r"(b[1]));
}

// ---------------------------------------------------------------------------
// K0: zero output + counters
// ---------------------------------------------------------------------------
__global__ void k_zero(float* __restrict__ out) {
    size_t i = (size_t)blockIdx.x * blockDim.x + threadIdx.x;
    size_t n4 = (size_t)TNUM * EDIM / 4;
    if (i < n4) ((float4*)out)[i] = make_float4(0.f, 0.f, 0.f, 0.f);
    if (blockIdx.x == 0 && threadIdx.x < NEXP) g_cnt[threadIdx.x] = 0;
}

// ---------------------------------------------------------------------------
// K1: router (exact fp32): logits, top-2, 2-way softmax, compact lists
// ---------------------------------------------------------------------------
__global__ __launch_bounds__(256) void k_router(const float* __restrict__ x,
                                                const float* __restrict__ Wr,
                                                const float* __restrict__ br) {
    int warp = (blockIdx.x * blockDim.x + threadIdx.x) >> 5;
    int lane = threadIdx.x & 31;
    if (warp >= TNUM) return;
    const float* xr = x + (size_t)warp * EDIM;

    float acc[NEXP];
#pragma unroll
    for (int n = 0; n < NEXP; n++) acc[n] = 0.f;
    for (int k = lane; k < EDIM; k += 32) {
        float xv = xr[k];
        const float4* w4 = (const float4*)(Wr + (size_t)k * NEXP);
        float4 a = w4[0], b = w4[1];
        acc[0] += xv * a.x; acc[1] += xv * a.y; acc[2] += xv * a.z; acc[3] += xv * a.w;
        acc[4] += xv * b.x; acc[5] += xv * b.y; acc[6] += xv * b.z; acc[7] += xv * b.w;
    }
#pragma unroll
    for (int n = 0; n < NEXP; n++)
#pragma unroll
        for (int o = 16; o > 0; o >>= 1)
            acc[n] += __shfl_xor_sync(0xffffffffu, acc[n], o);
    if (lane == 0) {
        float l[NEXP];
#pragma unroll
        for (int n = 0; n < NEXP; n++) l[n] = acc[n] + br[n];
        int i0 = 0;
#pragma unroll
        for (int n = 1; n < NEXP; n++) if (l[n] > l[i0]) i0 = n;
        int i1 = -1;
#pragma unroll
        for (int n = 0; n < NEXP; n++) {
            if (n == i0) continue;
            if (i1 < 0 || l[n] > l[i1]) i1 = n;
        }
        float d  = __expf(l[i1] - l[i0]);
        float w0 = 1.f / (1.f + d);
        float w1 = d * w0;
        int s0 = atomicAdd(&g_cnt[i0], 1);
        g_tok[i0 * CAP + s0] = warp;  g_wgt[i0 * CAP + s0] = w0;
        int s1 = atomicAdd(&g_cnt[i1], 1);
        g_tok[i1 * CAP + s1] = warp;  g_wgt[i1 * CAP + s1] = w1;
    }
}

// ---------------------------------------------------------------------------
// tf32 tensor-core grouped GEMMs. Tile 128x128xBK16, 256 thr = 8 warps (2x4),
// warp tile 64x32, mma m16n8k8. SMEM pad +8 -> fragment LDS conflict-free.
// ---------------------------------------------------------------------------
#define SPAD 136

// K2: hid = gelu(gather(x) @ W1[e] + b1[e])
__global__ __launch_bounds__(256, 2) void k_ffn1(const float* __restrict__ x,
                                                 const float* __restrict__ W1,
                                                 const float* __restrict__ b1) {
    int e   = blockIdx.z;
    int cnt = g_cnt[e];
    int m0  = blockIdx.y * 128;
    if (m0 >= cnt) return;
    int n0  = blockIdx.x * 128;

    __shared__ float As[16][SPAD];
    __shared__ float Bs[16][SPAD];
    __shared__ int   toks[128];

    int tid = threadIdx.x;
    if (tid < 128) {
        int m = m0 + tid;
        toks[tid] = (m < cnt) ? g_tok[e * CAP + m] : -1;
    }
    __syncthreads();

    const float* Wp = W1 + (size_t)e * EDIM * HDIM + n0;

    int lane = tid & 31, warp = tid >> 5;
    int gi = lane >> 2, qk = lane & 3;
    int wm = (warp >> 2) * 64, wn = (warp & 3) * 32;

    float acc[4][4][4];
#pragma unroll
    for (int i = 0; i < 4; i++)
#pragma unroll
        for (int j = 0; j < 4; j++)
#pragma unroll
            for (int r = 0; r < 4; r++) acc[i][j][r] = 0.f;

    for (int k0 = 0; k0 < EDIM; k0 += 16) {
        // A tile (gathered x rows), transposed As[k][m], tf32-rounded
#pragma unroll
        for (int i = 0; i < 2; i++) {
            int lin = tid + i * 256;
            int m = lin >> 2, kq = (lin & 3) * 4;
            int tok = toks[m];
            float4 v = make_float4(0.f, 0.f, 0.f, 0.f);
            if (tok >= 0) v = *(const float4*)(x + (size_t)tok * EDIM + k0 + kq);
            As[kq + 0][m] = to_tf32(v.x); As[kq + 1][m] = to_tf32(v.y);
            As[kq + 2][m] = to_tf32(v.z); As[kq + 3][m] = to_tf32(v.w);
        }
        // B tile: W1[e][k][n], n contiguous
#pragma unroll
        for (int i = 0; i < 2; i++) {
            int lin = tid + i * 256;
            int kk = lin >> 5, nq = (lin & 31) * 4;
            float4 v = *(const float4*)(Wp + (size_t)(k0 + kk) * HDIM + nq);
            Bs[kk][nq + 0] = to_tf32(v.x); Bs[kk][nq + 1] = to_tf32(v.y);
            Bs[kk][nq + 2] = to_tf32(v.z); Bs[kk][nq + 3] = to_tf32(v.w);
        }
        __syncthreads();

#pragma unroll
        for (int ks = 0; ks < 16; ks += 8) {
            unsigned a[4][4], b[4][2];
#pragma unroll
            for (int mi = 0; mi < 4; mi++) {
                int mb = wm + mi * 16 + gi;
                a[mi][0] = __float_as_uint(As[ks + qk][mb]);
                a[mi][1] = __float_as_uint(As[ks + qk][mb + 8]);
                a[mi][2] = __float_as_uint(As[ks + qk + 4][mb]);
                a[mi][3] = __float_as_uint(As[ks + qk + 4][mb + 8]);
            }
#pragma unroll
            for (int nj = 0; nj < 4; nj++) {
                int nb = wn + nj * 8 + gi;
                b[nj][0] = __float_as_uint(Bs[ks + qk][nb]);
                b[nj][1] = __float_as_uint(Bs[ks + qk + 4][nb]);
            }
#pragma unroll
            for (int mi = 0; mi < 4; mi++)
#pragma unroll
                for (int nj = 0; nj < 4; nj++)
                    mma_tf32(acc[mi][nj], a[mi], b[nj]);
        }
        __syncthreads();
    }

    // epilogue: +b1, exact GELU, store hid
#pragma unroll
    for (int nj = 0; nj < 4; nj++) {
        int n = n0 + wn + nj * 8 + qk * 2;
        float b1a = b1[(size_t)e * HDIM + n];
        float b1b = b1[(size_t)e * HDIM + n + 1];
#pragma unroll
        for (int mi = 0; mi < 4; mi++) {
#pragma unroll
            for (int h = 0; h < 2; h++) {
                int m = m0 + wm + mi * 16 + gi + h * 8;
                if (m >= cnt) continue;
                float2 v;
                v.x = gelu_exact(acc[mi][nj][h * 2 + 0] + b1a);
                v.y = gelu_exact(acc[mi][nj][h * 2 + 1] + b1b);
                *(float2*)(g_hid + ((size_t)e * CAP + m) * HDIM + n) = v;
            }
        }
    }
}

// K3: out[tok] += w * (hid @ W2[e] + b2[e])
__global__ __launch_bounds__(256, 2) void k_ffn2(const float* __restrict__ W2,
                                                 const float* __restrict__ b2,
                                                 float* __restrict__ out) {
    int e   = blockIdx.z;
    int cnt = g_cnt[e];
    int m0  = blockIdx.y * 128;
    if (m0 >= cnt) return;
    int n0  = blockIdx.x * 128;

    __shared__ float As[16][SPAD];
    __shared__ float Bs[16][SPAD];
    __shared__ int   toks[128];
    __shared__ float wts[128];

    int tid = threadIdx.x;
    if (tid < 128) {
        int m = m0 + tid;
        bool v = (m < cnt);
        toks[tid] = v ? g_tok[e * CAP + m] : -1;
        wts[tid]  = v ? g_wgt[e * CAP + m] : 0.f;
    }
    __syncthreads();

    const float* Ap = g_hid + (size_t)(e * CAP + m0) * HDIM;
    const float* Wp = W2 + (size_t)e * HDIM * EDIM + n0;
    int mlim = cnt - m0;

    int lane = tid & 31, warp = tid >> 5;
    int gi = lane >> 2, qk = lane & 3;
    int wm = (warp >> 2) * 64, wn = (warp & 3) * 32;

    float acc[4][4][4];
#pragma unroll
    for (int i = 0; i < 4; i++)
#pragma unroll
        for (int j = 0; j < 4; j++)
#pragma unroll
            for (int r = 0; r < 4; r++) acc[i][j][r] = 0.f;

    for (int k0 = 0; k0 < HDIM; k0 += 16) {
#pragma unroll
        for (int i = 0; i < 2; i++) {
            int lin = tid + i * 256;
            int m = lin >> 2, kq = (lin & 3) * 4;
            float4 v = make_float4(0.f, 0.f, 0.f, 0.f);
            if (m < mlim) v = *(const float4*)(Ap + (size_t)m * HDIM + k0 + kq);
            As[kq + 0][m] = to_tf32(v.x); As[kq + 1][m] = to_tf32(v.y);
            As[kq + 2][m] = to_tf32(v.z); As[kq + 3][m] = to_tf32(v.w);
        }
#pragma unroll
        for (int i = 0; i < 2; i++) {
            int lin = tid + i * 256;
            int kk = lin >> 5, nq = (lin & 31) * 4;
            float4 v = *(const float4*)(Wp + (size_t)(k0 + kk) * EDIM + nq);
            Bs[kk][nq + 0] = to_tf32(v.x); Bs[kk][nq + 1] = to_tf32(v.y);
            Bs[kk][nq + 2] = to_tf32(v.z); Bs[kk][nq + 3] = to_tf32(v.w);
        }
        __syncthreads();

#pragma unroll
        for (int ks = 0; ks < 16; ks += 8) {
            unsigned a[4][4], b[4][2];
#pragma unroll
            for (int mi = 0; mi < 4; mi++) {
                int mb = wm + mi * 16 + gi;
                a[mi][0] = __float_as_uint(As[ks + qk][mb]);
                a[mi][1] = __float_as_uint(As[ks + qk][mb + 8]);
                a[mi][2] = __float_as_uint(As[ks + qk + 4][mb]);
                a[mi][3] = __float_as_uint(As[ks + qk + 4][mb + 8]);
            }
#pragma unroll
            for (int nj = 0; nj < 4; nj++) {
                int nb = wn + nj * 8 + gi;
                b[nj][0] = __float_as_uint(Bs[ks + qk][nb]);
                b[nj][1] = __float_as_uint(Bs[ks + qk + 4][nb]);
            }
#pragma unroll
            for (int mi = 0; mi < 4; mi++)
#pragma unroll
                for (int nj = 0; nj < 4; nj++)
                    mma_tf32(acc[mi][nj], a[mi], b[nj]);
        }
        __syncthreads();
    }

#pragma unroll
    for (int nj = 0; nj < 4; nj++) {
        int n = n0 + wn + nj * 8 + qk * 2;
        float b2a = b2[(size_t)e * EDIM + n];
        float b2b = b2[(size_t)e * EDIM + n + 1];
#pragma unroll
        for (int mi = 0; mi < 4; mi++) {
#pragma unroll
            for (int h = 0; h < 2; h++) {
                int ml = wm + mi * 16 + gi + h * 8;
                int tok = toks[ml];
                if (tok < 0) continue;
                float w = wts[ml];
                float* op = out + (size_t)tok * EDIM + n;
                atomicAdd(op + 0, w * (acc[mi][nj][h * 2 + 0] + b2a));
                atomicAdd(op + 1, w * (acc[mi][nj][h * 2 + 1] + b2b));
            }
        }
    }
}

// ---------------------------------------------------------------------------
extern "C" void kernel_launch(void* const* d_in, const int* in_sizes, int n_in,
                              void* d_out, int out_size) {
    const float* x  = (const float*)d_in[0];
    const float* Wr = (const float*)d_in[1];
    const float* br = (const float*)d_in[2];
    const float* W1 = (const float*)d_in[3];
    const float* b1 = (const float*)d_in[4];
    const float* W2 = (const float*)d_in[5];
    const float* b2 = (const float*)d_in[6];
    float* out = (float*)d_out;
    (void)in_sizes; (void)n_in; (void)out_size;

    k_zero<<<4096, 256>>>(out);
    k_router<<<TNUM / 8, 256>>>(x, Wr, br);
    dim3 g1(HDIM / 128, CAP / 128, NEXP);   // (32, 32, 8), empty M-tiles early-exit
    k_ffn1<<<g1, 256>>>(x, W1, b1);
    dim3 g2(EDIM / 128, CAP / 128, NEXP);   // (8, 32, 8)
    k_ffn2<<<g2, 256>>>(W2, b2, out);
}

// round 6
// speedup vs baseline: 3.8338x; 1.6411x over previous
#include <cuda_runtime.h>
#include <cuda_fp16.h>
#include <math.h>

// Shapes: x[2,2048,1024] f32 -> T=4096, E=1024; Wr[1024,8]; W1[8,1024,4096];
// b1[8,4096]; W2[8,4096,1024]; b2[8,1024]; top_k=2.
#define TNUM 4096
#define EDIM 1024
#define NEXP 8
#define HDIM 4096
#define CAP  4096

// Device-global scratch (allocation-free rule). NEVER pass these as kernel
// arguments from host code — reference them from device code only.
__device__ __half g_xh [(size_t)TNUM * EDIM];            // fp16 x
__device__ __half g_w1t[(size_t)NEXP * HDIM * EDIM];     // W1^T: [e][n=H][k=E]
__device__ __half g_w2t[(size_t)NEXP * EDIM * HDIM];     // W2^T: [e][n=E][k=H]
__device__ __half g_hid[(size_t)NEXP * CAP * HDIM];      // fp16 hidden
__device__ int    g_cnt[NEXP];
__device__ int    g_tok[NEXP * CAP];
__device__ float  g_wgt[NEXP * CAP];

__device__ __forceinline__ float gelu_exact(float v) {
    return 0.5f * v * (1.0f + erff(v * 0.70710678118654752f));
}

__device__ __forceinline__ void mma_f16(float* c, const unsigned* a, const unsigned* b) {
    asm volatile(
        "mma.sync.aligned.m16n8k16.row.col.f32.f16.f16.f32 "
        "{%0,%1,%2,%3}, {%4,%5,%6,%7}, {%8,%9}, {%0,%1,%2,%3};"
        : "+f"(c[0]), "+f"(c[1]), "+f"(c[2]), "+f"(c[3])
        : "r"(a[0]), "r"(a[1]), "r"(a[2]), "r"(a[3]), "r"(b[0]), "r"(b[1]));
}

// ---------------------------------------------------------------------------
// K0: zero output + counters
// ---------------------------------------------------------------------------
__global__ void k_zero(float* __restrict__ out) {
    size_t i = (size_t)blockIdx.x * blockDim.x + threadIdx.x;
    size_t n4 = (size_t)TNUM * EDIM / 4;
    if (i < n4) ((float4*)out)[i] = make_float4(0.f, 0.f, 0.f, 0.f);
    if (blockIdx.x == 0 && threadIdx.x < NEXP) g_cnt[threadIdx.x] = 0;
}

// Kc: x f32 -> f16 (g_xh referenced in device code)
__global__ void k_convx(const float* __restrict__ x) {
    size_t i = (size_t)blockIdx.x * blockDim.x + threadIdx.x;
    if (i < (size_t)TNUM * EDIM / 2) {
        float2 v = ((const float2*)x)[i];
        ((half2*)g_xh)[i] = __floats2half2_rn(v.x, v.y);
    }
}

// Kw: W [e][K][N] f32 -> WT [e][N][K] f16 (32x32 smem transpose).
// Destination selected INSIDE device code (templated) — fixes the host-side
// device-symbol-as-argument bug that zeroed rounds 3/4.
template <int WHICH>  // 0 -> g_w1t (K=EDIM,N=HDIM), 1 -> g_w2t (K=HDIM,N=EDIM)
__global__ __launch_bounds__(256) void k_convW(const float* __restrict__ W) {
    const int K = WHICH ? HDIM : EDIM;
    const int N = WHICH ? EDIM : HDIM;
    __half* WT = WHICH ? g_w2t : g_w1t;

    __shared__ float s[32][33];
    int e = blockIdx.z;
    int k0 = blockIdx.y * 32, n0 = blockIdx.x * 32;
    const float* Wp = W + ((size_t)e * K + k0) * N + n0;
    __half* Tp = WT + ((size_t)e * N + n0) * K + k0;
    int tx = threadIdx.x & 31, ty = threadIdx.x >> 5;
#pragma unroll
    for (int i = 0; i < 32; i += 8)
        s[ty + i][tx] = Wp[(size_t)(ty + i) * N + tx];
    __syncthreads();
#pragma unroll
    for (int i = 0; i < 32; i += 8) {
        int n = ty + i;
        Tp[(size_t)n * K + tx] = __float2half_rn(s[tx][n]);
    }
}

// ---------------------------------------------------------------------------
// K1: router (exact fp32): logits, top-2, 2-way softmax, compact lists
// ---------------------------------------------------------------------------
__global__ __launch_bounds__(256) void k_router(const float* __restrict__ x,
                                                const float* __restrict__ Wr,
                                                const float* __restrict__ br) {
    int warp = (blockIdx.x * blockDim.x + threadIdx.x) >> 5;
    int lane = threadIdx.x & 31;
    if (warp >= TNUM) return;
    const float* xr = x + (size_t)warp * EDIM;

    float acc[NEXP];
#pragma unroll
    for (int n = 0; n < NEXP; n++) acc[n] = 0.f;
    for (int k = lane; k < EDIM; k += 32) {
        float xv = xr[k];
        const float4* w4 = (const float4*)(Wr + (size_t)k * NEXP);
        float4 a = w4[0], b = w4[1];
        acc[0] += xv * a.x; acc[1] += xv * a.y; acc[2] += xv * a.z; acc[3] += xv * a.w;
        acc[4] += xv * b.x; acc[5] += xv * b.y; acc[6] += xv * b.z; acc[7] += xv * b.w;
    }
#pragma unroll
    for (int n = 0; n < NEXP; n++)
#pragma unroll
        for (int o = 16; o > 0; o >>= 1)
            acc[n] += __shfl_xor_sync(0xffffffffu, acc[n], o);
    if (lane == 0) {
        float l[NEXP];
#pragma unroll
        for (int n = 0; n < NEXP; n++) l[n] = acc[n] + br[n];
        int i0 = 0;
#pragma unroll
        for (int n = 1; n < NEXP; n++) if (l[n] > l[i0]) i0 = n;
        int i1 = -1;
#pragma unroll
        for (int n = 0; n < NEXP; n++) {
            if (n == i0) continue;
            if (i1 < 0 || l[n] > l[i1]) i1 = n;
        }
        float d  = __expf(l[i1] - l[i0]);
        float w0 = 1.f / (1.f + d);
        float w1 = d * w0;
        int s0 = atomicAdd(&g_cnt[i0], 1);
        g_tok[i0 * CAP + s0] = warp;  g_wgt[i0 * CAP + s0] = w0;
        int s1 = atomicAdd(&g_cnt[i1], 1);
        g_tok[i1 * CAP + s1] = warp;  g_wgt[i1 * CAP + s1] = w1;
    }
}

// ---------------------------------------------------------------------------
// fp16 grouped GEMMs: 128x128 tile, BK=32, 256 thr (8 warps 2x4), warp 64x32,
// mma m16n8k16. Synchronous register-prefetch double buffer (1 bar/iter).
// SMEM rows padded to 40 halves: fragment LDS conflict-free.
// ---------------------------------------------------------------------------
#define BK 32
#define LDP 40

__device__ __forceinline__ void mma_stage(const __half As[128][LDP],
                                          const __half Bs[128][LDP],
                                          int wm, int wn, int gi, int qk,
                                          float acc[4][4][4]) {
#pragma unroll
    for (int ks = 0; ks < BK; ks += 16) {
        unsigned a[4][4], b[4][2];
#pragma unroll
        for (int mi = 0; mi < 4; mi++) {
            int r = wm + mi * 16 + gi;
            a[mi][0] = *(const unsigned*)&As[r][ks + qk * 2];
            a[mi][1] = *(const unsigned*)&As[r + 8][ks + qk * 2];
            a[mi][2] = *(const unsigned*)&As[r][ks + qk * 2 + 8];
            a[mi][3] = *(const unsigned*)&As[r + 8][ks + qk * 2 + 8];
        }
#pragma unroll
        for (int nj = 0; nj < 4; nj++) {
            int nb = wn + nj * 8 + gi;
            b[nj][0] = *(const unsigned*)&Bs[nb][ks + qk * 2];
            b[nj][1] = *(const unsigned*)&Bs[nb][ks + qk * 2 + 8];
        }
#pragma unroll
        for (int mi = 0; mi < 4; mi++)
#pragma unroll
            for (int nj = 0; nj < 4; nj++)
                mma_f16(acc[mi][nj], a[mi], b[nj]);
    }
}

// K2: hid = gelu(gather(x_h) @ W1T[e]^T + b1[e])
__global__ __launch_bounds__(256, 2) void k_ffn1(const float* __restrict__ b1) {
    int e   = blockIdx.z;
    int cnt = g_cnt[e];
    int m0  = blockIdx.y * 128;
    if (m0 >= cnt) return;
    int n0  = blockIdx.x * 128;

    __shared__ __align__(16) __half As[2][128][LDP];
    __shared__ __align__(16) __half Bs[2][128][LDP];
    __shared__ int toks[128];

    int tid = threadIdx.x;
    if (tid < 128) {
        int m = m0 + tid;
        toks[tid] = (m < cnt) ? g_tok[e * CAP + m] : -1;
    }
    __syncthreads();

    int lane = tid & 31, warp = tid >> 5;
    int gi = lane >> 2, qk = lane & 3;
    int wm = (warp >> 2) * 64, wn = (warp & 3) * 32;

    int lr = tid >> 1, lc = (tid & 1) * 16;
    int my_tok = toks[lr];
    const __half* asrc = g_xh + (size_t)max(my_tok, 0) * EDIM + lc;
    const __half* bsrc = g_w1t + ((size_t)e * HDIM + n0 + lr) * EDIM + lc;

    float acc[4][4][4];
#pragma unroll
    for (int i = 0; i < 4; i++)
#pragma unroll
        for (int j = 0; j < 4; j++)
#pragma unroll
            for (int r = 0; r < 4; r++) acc[i][j][r] = 0.f;

    float4 ra[2], rb[2];
    const float4 z4 = make_float4(0.f, 0.f, 0.f, 0.f);
#pragma unroll
    for (int i = 0; i < 2; i++) {
        ra[i] = (my_tok >= 0) ? *(const float4*)(asrc + i * 8) : z4;
        rb[i] = *(const float4*)(bsrc + i * 8);
    }

    const int KT = EDIM / BK;
    for (int kt = 0; kt < KT; kt++) {
        int cur = kt & 1;
#pragma unroll
        for (int i = 0; i < 2; i++) {
            *(float4*)&As[cur][lr][lc + i * 8] = ra[i];
            *(float4*)&Bs[cur][lr][lc + i * 8] = rb[i];
        }
        __syncthreads();
        if (kt + 1 < KT) {
            int k0 = (kt + 1) * BK;
#pragma unroll
            for (int i = 0; i < 2; i++) {
                ra[i] = (my_tok >= 0) ? *(const float4*)(asrc + k0 + i * 8) : z4;
                rb[i] = *(const float4*)(bsrc + k0 + i * 8);
            }
        }
        mma_stage(As[cur], Bs[cur], wm, wn, gi, qk, acc);
    }

    // epilogue: +b1, exact GELU, store hid (fp16)
#pragma unroll
    for (int nj = 0; nj < 4; nj++) {
        int n = n0 + wn + nj * 8 + qk * 2;
        float b1a = b1[(size_t)e * HDIM + n];
        float b1b = b1[(size_t)e * HDIM + n + 1];
#pragma unroll
        for (int mi = 0; mi < 4; mi++) {
#pragma unroll
            for (int h = 0; h < 2; h++) {
                int m = m0 + wm + mi * 16 + gi + h * 8;
                if (m >= cnt) continue;
                float vx = gelu_exact(acc[mi][nj][h * 2 + 0] + b1a);
                float vy = gelu_exact(acc[mi][nj][h * 2 + 1] + b1b);
                *(half2*)(g_hid + ((size_t)e * CAP + m) * HDIM + n) =
                    __floats2half2_rn(vx, vy);
            }
        }
    }
}

// K3: out[tok] += w * (hid @ W2T[e]^T + b2[e])
__global__ __launch_bounds__(256, 2) void k_ffn2(const float* __restrict__ b2,
                                                 float* __restrict__ out) {
    int e   = blockIdx.z;
    int cnt = g_cnt[e];
    int m0  = blockIdx.y * 128;
    if (m0 >= cnt) return;
    int n0  = blockIdx.x * 128;

    __shared__ __align__(16) __half As[2][128][LDP];
    __shared__ __align__(16) __half Bs[2][128][LDP];
    __shared__ int   toks[128];
    __shared__ float wts[128];

    int tid = threadIdx.x;
    if (tid < 128) {
        int m = m0 + tid;
        bool v = (m < cnt);
        toks[tid] = v ? g_tok[e * CAP + m] : -1;
        wts[tid]  = v ? g_wgt[e * CAP + m] : 0.f;
    }
    __syncthreads();

    int mlim = cnt - m0;
    int lane = tid & 31, warp = tid >> 5;
    int gi = lane >> 2, qk = lane & 3;
    int wm = (warp >> 2) * 64, wn = (warp & 3) * 32;

    int lr = tid >> 1, lc = (tid & 1) * 16;
    bool mval = (lr < mlim);
    const __half* asrc = g_hid + ((size_t)e * CAP + m0 + (mval ? lr : 0)) * HDIM + lc;
    const __half* bsrc = g_w2t + ((size_t)e * EDIM + n0 + lr) * HDIM + lc;

    float acc[4][4][4];
#pragma unroll
    for (int i = 0; i < 4; i++)
#pragma unroll
        for (int j = 0; j < 4; j++)
#pragma unroll
            for (int r = 0; r < 4; r++) acc[i][j][r] = 0.f;

    float4 ra[2], rb[2];
    const float4 z4 = make_float4(0.f, 0.f, 0.f, 0.f);
#pragma unroll
    for (int i = 0; i < 2; i++) {
        ra[i] = mval ? *(const float4*)(asrc + i * 8) : z4;
        rb[i] = *(const float4*)(bsrc + i * 8);
    }

    const int KT = HDIM / BK;
    for (int kt = 0; kt < KT; kt++) {
        int cur = kt & 1;
#pragma unroll
        for (int i = 0; i < 2; i++) {
            *(float4*)&As[cur][lr][lc + i * 8] = ra[i];
            *(float4*)&Bs[cur][lr][lc + i * 8] = rb[i];
        }
        __syncthreads();
        if (kt + 1 < KT) {
            int k0 = (kt + 1) * BK;
#pragma unroll
            for (int i = 0; i < 2; i++) {
                ra[i] = mval ? *(const float4*)(asrc + k0 + i * 8) : z4;
                rb[i] = *(const float4*)(bsrc + k0 + i * 8);
            }
        }
        mma_stage(As[cur], Bs[cur], wm, wn, gi, qk, acc);
    }

#pragma unroll
    for (int nj = 0; nj < 4; nj++) {
        int n = n0 + wn + nj * 8 + qk * 2;
        float b2a = b2[(size_t)e * EDIM + n];
        float b2b = b2[(size_t)e * EDIM + n + 1];
#pragma unroll
        for (int mi = 0; mi < 4; mi++) {
#pragma unroll
            for (int h = 0; h < 2; h++) {
                int ml = wm + mi * 16 + gi + h * 8;
                int tok = toks[ml];
                if (tok < 0) continue;
                float w = wts[ml];
                float* op = out + (size_t)tok * EDIM + n;
                atomicAdd(op + 0, w * (acc[mi][nj][h * 2 + 0] + b2a));
                atomicAdd(op + 1, w * (acc[mi][nj][h * 2 + 1] + b2b));
            }
        }
    }
}

// ---------------------------------------------------------------------------
extern "C" void kernel_launch(void* const* d_in, const int* in_sizes, int n_in,
                              void* d_out, int out_size) {
    const float* x  = (const float*)d_in[0];
    const float* Wr = (const float*)d_in[1];
    const float* br = (const float*)d_in[2];
    const float* W1 = (const float*)d_in[3];
    const float* b1 = (const float*)d_in[4];
    const float* W2 = (const float*)d_in[5];
    const float* b2 = (const float*)d_in[6];
    float* out = (float*)d_out;
    (void)in_sizes; (void)n_in; (void)out_size;

    k_zero<<<4096, 256>>>(out);
    k_convx<<<(TNUM * EDIM / 2 + 255) / 256, 256>>>(x);
    {   // W1: K=EDIM, N=HDIM -> g_w1t [e][HDIM][EDIM]
        dim3 g(HDIM / 32, EDIM / 32, NEXP);
        k_convW<0><<<g, 256>>>(W1);
    }
    {   // W2: K=HDIM, N=EDIM -> g_w2t [e][EDIM][HDIM]
        dim3 g(EDIM / 32, HDIM / 32, NEXP);
        k_convW<1><<<g, 256>>>(W2);
    }
    k_router<<<TNUM / 8, 256>>>(x, Wr, br);
    dim3 g1(HDIM / 128, CAP / 128, NEXP);   // (32, 32, 8), empty M-tiles early-exit
    k_ffn1<<<g1, 256>>>(b1);
    dim3 g2(EDIM / 128, CAP / 128, NEXP);   // (8, 32, 8)
    k_ffn2<<<g2, 256>>>(b2, out);
}

// round 7
// speedup vs baseline: 4.7058x; 1.2275x over previous
#include <cuda_runtime.h>
#include <cuda_fp16.h>
#include <math.h>

// Shapes: x[2,2048,1024] f32 -> T=4096, E=1024; Wr[1024,8]; W1[8,1024,4096];
// b1[8,4096]; W2[8,4096,1024]; b2[8,1024]; top_k=2.
#define TNUM 4096
#define EDIM 1024
#define NEXP 8
#define HDIM 4096
#define CAP  4096

// Device-global scratch (allocation-free rule). NEVER pass these as kernel
// arguments from host code — reference them from device code only.
__device__ __half g_xh [(size_t)TNUM * EDIM];            // fp16 x
__device__ __half g_w1t[(size_t)NEXP * HDIM * EDIM];     // W1^T: [e][n=H][k=E]
__device__ __half g_w2t[(size_t)NEXP * EDIM * HDIM];     // W2^T: [e][n=E][k=H]
__device__ __half g_hid[(size_t)NEXP * CAP * HDIM];      // fp16 hidden
__device__ int    g_cnt[NEXP];
__device__ int    g_tok[NEXP * CAP];
__device__ float  g_wgt[NEXP * CAP];

__device__ __forceinline__ float gelu_exact(float v) {
    return 0.5f * v * (1.0f + erff(v * 0.70710678118654752f));
}

__device__ __forceinline__ void mma_f16(float* c, const unsigned* a, const unsigned* b) {
    asm volatile(
        "mma.sync.aligned.m16n8k16.row.col.f32.f16.f16.f32 "
        "{%0,%1,%2,%3}, {%4,%5,%6,%7}, {%8,%9}, {%0,%1,%2,%3};"
        : "+f"(c[0]), "+f"(c[1]), "+f"(c[2]), "+f"(c[3])
        : "r"(a[0]), "r"(a[1]), "r"(a[2]), "r"(a[3]), "r"(b[0]), "r"(b[1]));
}

__device__ __forceinline__ void ldsm_x4(unsigned* d, unsigned addr) {
    asm volatile("ldmatrix.sync.aligned.m8n8.x4.shared.b16 {%0,%1,%2,%3}, [%4];"
                 : "=r"(d[0]), "=r"(d[1]), "=r"(d[2]), "=r"(d[3]) : "r"(addr));
}

// ---------------------------------------------------------------------------
// K0: zero output + counters
// ---------------------------------------------------------------------------
__global__ void k_zero(float* __restrict__ out) {
    size_t i = (size_t)blockIdx.x * blockDim.x + threadIdx.x;
    size_t n4 = (size_t)TNUM * EDIM / 4;
    if (i < n4) ((float4*)out)[i] = make_float4(0.f, 0.f, 0.f, 0.f);
    if (blockIdx.x == 0 && threadIdx.x < NEXP) g_cnt[threadIdx.x] = 0;
}

// Kc: x f32 -> f16
__global__ void k_convx(const float* __restrict__ x) {
    size_t i = (size_t)blockIdx.x * blockDim.x + threadIdx.x;
    if (i < (size_t)TNUM * EDIM / 2) {
        float2 v = ((const float2*)x)[i];
        ((half2*)g_xh)[i] = __floats2half2_rn(v.x, v.y);
    }
}

// Kw: W [e][K][N] f32 -> WT [e][N][K] f16; destination chosen in device code.
template <int WHICH>  // 0 -> g_w1t (K=EDIM,N=HDIM), 1 -> g_w2t (K=HDIM,N=EDIM)
__global__ __launch_bounds__(256) void k_convW(const float* __restrict__ W) {
    const int K = WHICH ? HDIM : EDIM;
    const int N = WHICH ? EDIM : HDIM;
    __half* WT = WHICH ? g_w2t : g_w1t;

    __shared__ float s[32][33];
    int e = blockIdx.z;
    int k0 = blockIdx.y * 32, n0 = blockIdx.x * 32;
    const float* Wp = W + ((size_t)e * K + k0) * N + n0;
    __half* Tp = WT + ((size_t)e * N + n0) * K + k0;
    int tx = threadIdx.x & 31, ty = threadIdx.x >> 5;
#pragma unroll
    for (int i = 0; i < 32; i += 8)
        s[ty + i][tx] = Wp[(size_t)(ty + i) * N + tx];
    __syncthreads();
#pragma unroll
    for (int i = 0; i < 32; i += 8) {
        int n = ty + i;
        Tp[(size_t)n * K + tx] = __float2half_rn(s[tx][n]);
    }
}

// ---------------------------------------------------------------------------
// K1: router (exact fp32): logits, top-2, 2-way softmax, compact lists
// ---------------------------------------------------------------------------
__global__ __launch_bounds__(256) void k_router(const float* __restrict__ x,
                                                const float* __restrict__ Wr,
                                                const float* __restrict__ br) {
    int warp = (blockIdx.x * blockDim.x + threadIdx.x) >> 5;
    int lane = threadIdx.x & 31;
    if (warp >= TNUM) return;
    const float* xr = x + (size_t)warp * EDIM;

    float acc[NEXP];
#pragma unroll
    for (int n = 0; n < NEXP; n++) acc[n] = 0.f;
    for (int k = lane; k < EDIM; k += 32) {
        float xv = xr[k];
        const float4* w4 = (const float4*)(Wr + (size_t)k * NEXP);
        float4 a = w4[0], b = w4[1];
        acc[0] += xv * a.x; acc[1] += xv * a.y; acc[2] += xv * a.z; acc[3] += xv * a.w;
        acc[4] += xv * b.x; acc[5] += xv * b.y; acc[6] += xv * b.z; acc[7] += xv * b.w;
    }
#pragma unroll
    for (int n = 0; n < NEXP; n++)
#pragma unroll
        for (int o = 16; o > 0; o >>= 1)
            acc[n] += __shfl_xor_sync(0xffffffffu, acc[n], o);
    if (lane == 0) {
        float l[NEXP];
#pragma unroll
        for (int n = 0; n < NEXP; n++) l[n] = acc[n] + br[n];
        int i0 = 0;
#pragma unroll
        for (int n = 1; n < NEXP; n++) if (l[n] > l[i0]) i0 = n;
        int i1 = -1;
#pragma unroll
        for (int n = 0; n < NEXP; n++) {
            if (n == i0) continue;
            if (i1 < 0 || l[n] > l[i1]) i1 = n;
        }
        float d  = __expf(l[i1] - l[i0]);
        float w0 = 1.f / (1.f + d);
        float w1 = d * w0;
        int s0 = atomicAdd(&g_cnt[i0], 1);
        g_tok[i0 * CAP + s0] = warp;  g_wgt[i0 * CAP + s0] = w0;
        int s1 = atomicAdd(&g_cnt[i1], 1);
        g_tok[i1 * CAP + s1] = warp;  g_wgt[i1 * CAP + s1] = w1;
    }
}

// ---------------------------------------------------------------------------
// fp16 grouped GEMMs: 128x128 tile, BK=32, 256 thr (8 warps 2x4), warp 64x32,
// mma m16n8k16, ldmatrix fragment loads. Unpadded 64B rows with XOR chunk
// swizzle pc = c ^ ((r>>1)&3): stores and all LDSM phases conflict-free.
// ---------------------------------------------------------------------------
#define BK 32

__device__ __forceinline__ unsigned sw_off(int r, int c) {  // offset in halves
    return (unsigned)(r * BK + ((c ^ ((r >> 1) & 3)) << 3));
}

__device__ __forceinline__ void mma_stage(const __half* As, const __half* Bs,
                                          int wm, int wn, int lane,
                                          float acc[4][4][4]) {
    unsigned abase = (unsigned)__cvta_generic_to_shared(As);
    unsigned bbase = (unsigned)__cvta_generic_to_shared(Bs);
    int arow = lane & 15;
    int brow = ((lane >> 4) << 3) + (lane & 7);
#pragma unroll
    for (int ks = 0; ks < BK; ks += 16) {
        unsigned a[4][4], b[2][4];
        int achunk = (ks >> 3) + (lane >> 4);
        int bchunk = (ks >> 3) + ((lane >> 3) & 1);
#pragma unroll
        for (int mi = 0; mi < 4; mi++)
            ldsm_x4(a[mi], abase + 2u * sw_off(wm + mi * 16 + arow, achunk));
#pragma unroll
        for (int nj2 = 0; nj2 < 2; nj2++)
            ldsm_x4(b[nj2], bbase + 2u * sw_off(wn + nj2 * 16 + brow, bchunk));
#pragma unroll
        for (int mi = 0; mi < 4; mi++)
#pragma unroll
            for (int nj = 0; nj < 4; nj++)
                mma_f16(acc[mi][nj], a[mi], &b[nj >> 1][(nj & 1) * 2]);
    }
}

// K2: hid = gelu(gather(x_h) @ W1T[e]^T + b1[e])
__global__ __launch_bounds__(256, 2) void k_ffn1(const float* __restrict__ b1) {
    int e   = blockIdx.z;
    int cnt = g_cnt[e];
    int m0  = blockIdx.y * 128;
    if (m0 >= cnt) return;
    int n0  = blockIdx.x * 128;

    __shared__ __align__(16) __half As[2][128 * BK];
    __shared__ __align__(16) __half Bs[2][128 * BK];
    __shared__ int toks[128];

    int tid = threadIdx.x;
    if (tid < 128) {
        int m = m0 + tid;
        toks[tid] = (m < cnt) ? g_tok[e * CAP + m] : -1;
    }
    __syncthreads();

    int lane = tid & 31, warp = tid >> 5;
    int gi = lane >> 2, qk = lane & 3;
    int wm = (warp >> 2) * 64, wn = (warp & 3) * 32;

    int lr = tid >> 1, c0 = (tid & 1) * 2, lc = (tid & 1) * 16;
    int my_tok = toks[lr];
    const __half* asrc = g_xh + (size_t)max(my_tok, 0) * EDIM + lc;
    const __half* bsrc = g_w1t + ((size_t)e * HDIM + n0 + lr) * EDIM + lc;
    unsigned so0 = sw_off(lr, c0), so1 = sw_off(lr, c0 + 1);

    float acc[4][4][4];
#pragma unroll
    for (int i = 0; i < 4; i++)
#pragma unroll
        for (int j = 0; j < 4; j++)
#pragma unroll
            for (int r = 0; r < 4; r++) acc[i][j][r] = 0.f;

    float4 ra[2], rb[2];
    const float4 z4 = make_float4(0.f, 0.f, 0.f, 0.f);
#pragma unroll
    for (int i = 0; i < 2; i++) {
        ra[i] = (my_tok >= 0) ? *(const float4*)(asrc + i * 8) : z4;
        rb[i] = *(const float4*)(bsrc + i * 8);
    }

    const int KT = EDIM / BK;
    for (int kt = 0; kt < KT; kt++) {
        int cur = kt & 1;
        *(float4*)(As[cur] + so0) = ra[0];
        *(float4*)(As[cur] + so1) = ra[1];
        *(float4*)(Bs[cur] + so0) = rb[0];
        *(float4*)(Bs[cur] + so1) = rb[1];
        __syncthreads();
        if (kt + 1 < KT) {
            int k0 = (kt + 1) * BK;
#pragma unroll
            for (int i = 0; i < 2; i++) {
                ra[i] = (my_tok >= 0) ? *(const float4*)(asrc + k0 + i * 8) : z4;
                rb[i] = *(const float4*)(bsrc + k0 + i * 8);
            }
        }
        mma_stage(As[cur], Bs[cur], wm, wn, lane, acc);
    }

    // epilogue: +b1, exact GELU, store hid (fp16)
#pragma unroll
    for (int nj = 0; nj < 4; nj++) {
        int n = n0 + wn + nj * 8 + qk * 2;
        float b1a = b1[(size_t)e * HDIM + n];
        float b1b = b1[(size_t)e * HDIM + n + 1];
#pragma unroll
        for (int mi = 0; mi < 4; mi++) {
#pragma unroll
            for (int h = 0; h < 2; h++) {
                int m = m0 + wm + mi * 16 + gi + h * 8;
                if (m >= cnt) continue;
                float vx = gelu_exact(acc[mi][nj][h * 2 + 0] + b1a);
                float vy = gelu_exact(acc[mi][nj][h * 2 + 1] + b1b);
                *(half2*)(g_hid + ((size_t)e * CAP + m) * HDIM + n) =
                    __floats2half2_rn(vx, vy);
            }
        }
    }
}

// K3: out[tok] += w * (hid @ W2T[e]^T + b2[e])
__global__ __launch_bounds__(256, 2) void k_ffn2(const float* __restrict__ b2,
                                                 float* __restrict__ out) {
    int e   = blockIdx.z;
    int cnt = g_cnt[e];
    int m0  = blockIdx.y * 128;
    if (m0 >= cnt) return;
    int n0  = blockIdx.x * 128;

    __shared__ __align__(16) __half As[2][128 * BK];
    __shared__ __align__(16) __half Bs[2][128 * BK];
    __shared__ int   toks[128];
    __shared__ float wts[128];

    int tid = threadIdx.x;
    if (tid < 128) {
        int m = m0 + tid;
        bool v = (m < cnt);
        toks[tid] = v ? g_tok[e * CAP + m] : -1;
        wts[tid]  = v ? g_wgt[e * CAP + m] : 0.f;
    }
    __syncthreads();

    int mlim = cnt - m0;
    int lane = tid & 31, warp = tid >> 5;
    int gi = lane >> 2, qk = lane & 3;
    int wm = (warp >> 2) * 64, wn = (warp & 3) * 32;

    int lr = tid >> 1, c0 = (tid & 1) * 2, lc = (tid & 1) * 16;
    bool mval = (lr < mlim);
    const __half* asrc = g_hid + ((size_t)e * CAP + m0 + (mval ? lr : 0)) * HDIM + lc;
    const __half* bsrc = g_w2t + ((size_t)e * EDIM + n0 + lr) * HDIM + lc;
    unsigned so0 = sw_off(lr, c0), so1 = sw_off(lr, c0 + 1);

    float acc[4][4][4];
#pragma unroll
    for (int i = 0; i < 4; i++)
#pragma unroll
        for (int j = 0; j < 4; j++)
#pragma unroll
            for (int r = 0; r < 4; r++) acc[i][j][r] = 0.f;

    float4 ra[2], rb[2];
    const float4 z4 = make_float4(0.f, 0.f, 0.f, 0.f);
#pragma unroll
    for (int i = 0; i < 2; i++) {
        ra[i] = mval ? *(const float4*)(asrc + i * 8) : z4;
        rb[i] = *(const float4*)(bsrc + i * 8);
    }

    const int KT = HDIM / BK;
    for (int kt = 0; kt < KT; kt++) {
        int cur = kt & 1;
        *(float4*)(As[cur] + so0) = ra[0];
        *(float4*)(As[cur] + so1) = ra[1];
        *(float4*)(Bs[cur] + so0) = rb[0];
        *(float4*)(Bs[cur] + so1) = rb[1];
        __syncthreads();
        if (kt + 1 < KT) {
            int k0 = (kt + 1) * BK;
#pragma unroll
            for (int i = 0; i < 2; i++) {
                ra[i] = mval ? *(const float4*)(asrc + k0 + i * 8) : z4;
                rb[i] = *(const float4*)(bsrc + k0 + i * 8);
            }
        }
        mma_stage(As[cur], Bs[cur], wm, wn, lane, acc);
    }

#pragma unroll
    for (int nj = 0; nj < 4; nj++) {
        int n = n0 + wn + nj * 8 + qk * 2;
        float b2a = b2[(size_t)e * EDIM + n];
        float b2b = b2[(size_t)e * EDIM + n + 1];
#pragma unroll
        for (int mi = 0; mi < 4; mi++) {
#pragma unroll
            for (int h = 0; h < 2; h++) {
                int ml = wm + mi * 16 + gi + h * 8;
                int tok = toks[ml];
                if (tok < 0) continue;
                float w = wts[ml];
                float* op = out + (size_t)tok * EDIM + n;
                atomicAdd(op + 0, w * (acc[mi][nj][h * 2 + 0] + b2a));
                atomicAdd(op + 1, w * (acc[mi][nj][h * 2 + 1] + b2b));
            }
        }
    }
}

// ---------------------------------------------------------------------------
extern "C" void kernel_launch(void* const* d_in, const int* in_sizes, int n_in,
                              void* d_out, int out_size) {
    const float* x  = (const float*)d_in[0];
    const float* Wr = (const float*)d_in[1];
    const float* br = (const float*)d_in[2];
    const float* W1 = (const float*)d_in[3];
    const float* b1 = (const float*)d_in[4];
    const float* W2 = (const float*)d_in[5];
    const float* b2 = (const float*)d_in[6];
    float* out = (float*)d_out;
    (void)in_sizes; (void)n_in; (void)out_size;

    k_zero<<<4096, 256>>>(out);
    k_convx<<<(TNUM * EDIM / 2 + 255) / 256, 256>>>(x);
    {   dim3 g(HDIM / 32, EDIM / 32, NEXP);
        k_convW<0><<<g, 256>>>(W1); }
    {   dim3 g(EDIM / 32, HDIM / 32, NEXP);
        k_convW<1><<<g, 256>>>(W2); }
    k_router<<<TNUM / 8, 256>>>(x, Wr, br);
    dim3 g1(HDIM / 128, CAP / 128, NEXP);
    k_ffn1<<<g1, 256>>>(b1);
    dim3 g2(EDIM / 128, CAP / 128, NEXP);
    k_ffn2<<<g2, 256>>>(b2, out);
}

// round 8
// speedup vs baseline: 5.4135x; 1.1504x over previous
#include <cuda_runtime.h>
#include <cuda_fp16.h>
#include <math.h>

// Shapes: x[2,2048,1024] f32 -> T=4096, E=1024; Wr[1024,8]; W1[8,1024,4096];
// b1[8,4096]; W2[8,4096,1024]; b2[8,1024]; top_k=2.
#define TNUM 4096
#define EDIM 1024
#define NEXP 8
#define HDIM 4096
#define CAP  4096

// Device-global scratch (allocation-free rule). NEVER pass these as kernel
// arguments from host code — reference them from device code only.
__device__ __half g_xh [(size_t)TNUM * EDIM];            // fp16 x
__device__ __half g_w1t[(size_t)NEXP * HDIM * EDIM];     // W1^T: [e][n=H][k=E]
__device__ __half g_w2t[(size_t)NEXP * EDIM * HDIM];     // W2^T: [e][n=E][k=H]
__device__ __half g_hid[(size_t)NEXP * CAP * HDIM];      // fp16 hidden
__device__ int    g_cnt[NEXP];
__device__ int    g_tok[NEXP * CAP];
__device__ float  g_wgt[NEXP * CAP];

__device__ __forceinline__ float gelu_exact(float v) {
    return 0.5f * v * (1.0f + erff(v * 0.70710678118654752f));
}

__device__ __forceinline__ void mma_f16(float* c, const unsigned* a, const unsigned* b) {
    asm volatile(
        "mma.sync.aligned.m16n8k16.row.col.f32.f16.f16.f32 "
        "{%0,%1,%2,%3}, {%4,%5,%6,%7}, {%8,%9}, {%0,%1,%2,%3};"
        : "+f"(c[0]), "+f"(c[1]), "+f"(c[2]), "+f"(c[3])
        : "r"(a[0]), "r"(a[1]), "r"(a[2]), "r"(a[3]), "r"(b[0]), "r"(b[1]));
}

__device__ __forceinline__ void ldsm_x4(unsigned* d, unsigned addr) {
    asm volatile("ldmatrix.sync.aligned.m8n8.x4.shared.b16 {%0,%1,%2,%3}, [%4];"
                 : "=r"(d[0]), "=r"(d[1]), "=r"(d[2]), "=r"(d[3]) : "r"(addr));
}

__device__ __forceinline__ void cp16(void* smem, const void* gmem, int src_bytes) {
    unsigned s = (unsigned)__cvta_generic_to_shared(smem);
    asm volatile("cp.async.cg.shared.global [%0], [%1], 16, %2;\n"
                 :: "r"(s), "l"(gmem), "r"(src_bytes));
}
__device__ __forceinline__ void cp_commit() { asm volatile("cp.async.commit_group;\n"); }
__device__ __forceinline__ void cp_wait1()  { asm volatile("cp.async.wait_group 1;\n"); }

// ---------------------------------------------------------------------------
// K0: zero output + counters
// ---------------------------------------------------------------------------
__global__ void k_zero(float* __restrict__ out) {
    size_t i = (size_t)blockIdx.x * blockDim.x + threadIdx.x;
    size_t n4 = (size_t)TNUM * EDIM / 4;
    if (i < n4) ((float4*)out)[i] = make_float4(0.f, 0.f, 0.f, 0.f);
    if (blockIdx.x == 0 && threadIdx.x < NEXP) g_cnt[threadIdx.x] = 0;
}

// Kc: x f32 -> f16
__global__ void k_convx(const float* __restrict__ x) {
    size_t i = (size_t)blockIdx.x * blockDim.x + threadIdx.x;
    if (i < (size_t)TNUM * EDIM / 2) {
        float2 v = ((const float2*)x)[i];
        ((half2*)g_xh)[i] = __floats2half2_rn(v.x, v.y);
    }
}

// Kw: W [e][K][N] f32 -> WT [e][N][K] f16; destination chosen in device code.
template <int WHICH>  // 0 -> g_w1t (K=EDIM,N=HDIM), 1 -> g_w2t (K=HDIM,N=EDIM)
__global__ __launch_bounds__(256) void k_convW(const float* __restrict__ W) {
    const int K = WHICH ? HDIM : EDIM;
    const int N = WHICH ? EDIM : HDIM;
    __half* WT = WHICH ? g_w2t : g_w1t;

    __shared__ float s[32][33];
    int e = blockIdx.z;
    int k0 = blockIdx.y * 32, n0 = blockIdx.x * 32;
    const float* Wp = W + ((size_t)e * K + k0) * N + n0;
    __half* Tp = WT + ((size_t)e * N + n0) * K + k0;
    int tx = threadIdx.x & 31, ty = threadIdx.x >> 5;
#pragma unroll
    for (int i = 0; i < 32; i += 8)
        s[ty + i][tx] = Wp[(size_t)(ty + i) * N + tx];
    __syncthreads();
#pragma unroll
    for (int i = 0; i < 32; i += 8) {
        int n = ty + i;
        Tp[(size_t)n * K + tx] = __float2half_rn(s[tx][n]);
    }
}

// ---------------------------------------------------------------------------
// K1: router (exact fp32): logits, top-2, 2-way softmax, compact lists
// ---------------------------------------------------------------------------
__global__ __launch_bounds__(256) void k_router(const float* __restrict__ x,
                                                const float* __restrict__ Wr,
                                                const float* __restrict__ br) {
    int warp = (blockIdx.x * blockDim.x + threadIdx.x) >> 5;
    int lane = threadIdx.x & 31;
    if (warp >= TNUM) return;
    const float* xr = x + (size_t)warp * EDIM;

    float acc[NEXP];
#pragma unroll
    for (int n = 0; n < NEXP; n++) acc[n] = 0.f;
    for (int k = lane; k < EDIM; k += 32) {
        float xv = xr[k];
        const float4* w4 = (const float4*)(Wr + (size_t)k * NEXP);
        float4 a = w4[0], b = w4[1];
        acc[0] += xv * a.x; acc[1] += xv * a.y; acc[2] += xv * a.z; acc[3] += xv * a.w;
        acc[4] += xv * b.x; acc[5] += xv * b.y; acc[6] += xv * b.z; acc[7] += xv * b.w;
    }
#pragma unroll
    for (int n = 0; n < NEXP; n++)
#pragma unroll
        for (int o = 16; o > 0; o >>= 1)
            acc[n] += __shfl_xor_sync(0xffffffffu, acc[n], o);
    if (lane == 0) {
        float l[NEXP];
#pragma unroll
        for (int n = 0; n < NEXP; n++) l[n] = acc[n] + br[n];
        int i0 = 0;
#pragma unroll
        for (int n = 1; n < NEXP; n++) if (l[n] > l[i0]) i0 = n;
        int i1 = -1;
#pragma unroll
        for (int n = 0; n < NEXP; n++) {
            if (n == i0) continue;
            if (i1 < 0 || l[n] > l[i1]) i1 = n;
        }
        float d  = __expf(l[i1] - l[i0]);
        float w0 = 1.f / (1.f + d);
        float w1 = d * w0;
        int s0 = atomicAdd(&g_cnt[i0], 1);
        g_tok[i0 * CAP + s0] = warp;  g_wgt[i0 * CAP + s0] = w0;
        int s1 = atomicAdd(&g_cnt[i1], 1);
        g_tok[i1 * CAP + s1] = warp;  g_wgt[i1 * CAP + s1] = w1;
    }
}

// ---------------------------------------------------------------------------
// fp16 grouped GEMMs: 128x128 tile, BK=32, 256 thr (8 warps 2x4), warp 64x32,
// mma m16n8k16, ldmatrix fragment loads, 3-stage cp.async pipeline.
// Unpadded 64B rows, XOR chunk swizzle pc = c ^ ((r>>1)&3): conflict-free.
// ---------------------------------------------------------------------------
#define BK 32
#define NSTG 3

__device__ __forceinline__ unsigned sw_off(int r, int c) {  // offset in halves
    return (unsigned)(r * BK + ((c ^ ((r >> 1) & 3)) << 3));
}

__device__ __forceinline__ void mma_stage(const __half* As, const __half* Bs,
                                          int wm, int wn, int lane,
                                          float acc[4][4][4]) {
    unsigned abase = (unsigned)__cvta_generic_to_shared(As);
    unsigned bbase = (unsigned)__cvta_generic_to_shared(Bs);
    int arow = lane & 15;
    int brow = ((lane >> 4) << 3) + (lane & 7);
#pragma unroll
    for (int ks = 0; ks < BK; ks += 16) {
        unsigned a[4][4], b[2][4];
        int achunk = (ks >> 3) + (lane >> 4);
        int bchunk = (ks >> 3) + ((lane >> 3) & 1);
#pragma unroll
        for (int mi = 0; mi < 4; mi++)
            ldsm_x4(a[mi], abase + 2u * sw_off(wm + mi * 16 + arow, achunk));
#pragma unroll
        for (int nj2 = 0; nj2 < 2; nj2++)
            ldsm_x4(b[nj2], bbase + 2u * sw_off(wn + nj2 * 16 + brow, bchunk));
#pragma unroll
        for (int mi = 0; mi < 4; mi++)
#pragma unroll
            for (int nj = 0; nj < 4; nj++)
                mma_f16(acc[mi][nj], a[mi], &b[nj >> 1][(nj & 1) * 2]);
    }
}

// K2: hid = gelu(gather(x_h) @ W1T[e]^T + b1[e])
__global__ __launch_bounds__(256, 2) void k_ffn1(const float* __restrict__ b1) {
    int e   = blockIdx.z;
    int cnt = g_cnt[e];
    int m0  = blockIdx.y * 128;
    if (m0 >= cnt) return;
    int n0  = blockIdx.x * 128;

    __shared__ __align__(16) __half As[NSTG][128 * BK];
    __shared__ __align__(16) __half Bs[NSTG][128 * BK];
    __shared__ int toks[128];

    int tid = threadIdx.x;
    if (tid < 128) {
        int m = m0 + tid;
        toks[tid] = (m < cnt) ? g_tok[e * CAP + m] : -1;
    }
    __syncthreads();

    int lane = tid & 31, warp = tid >> 5;
    int gi = lane >> 2, qk = lane & 3;
    int wm = (warp >> 2) * 64, wn = (warp & 3) * 32;

    int lr = tid >> 1, c0 = (tid & 1) * 2, lc = (tid & 1) * 16;
    int my_tok = toks[lr];
    int abytes = (my_tok >= 0) ? 16 : 0;
    const __half* asrc = g_xh + (size_t)max(my_tok, 0) * EDIM + lc;
    const __half* bsrc = g_w1t + ((size_t)e * HDIM + n0 + lr) * EDIM + lc;
    unsigned so0 = sw_off(lr, c0), so1 = sw_off(lr, c0 + 1);

    float acc[4][4][4];
#pragma unroll
    for (int i = 0; i < 4; i++)
#pragma unroll
        for (int j = 0; j < 4; j++)
#pragma unroll
            for (int r = 0; r < 4; r++) acc[i][j][r] = 0.f;

    auto load_stage = [&](int buf, int k0) {
        cp16(As[buf] + so0, asrc + k0,     abytes);
        cp16(As[buf] + so1, asrc + k0 + 8, abytes);
        cp16(Bs[buf] + so0, bsrc + k0,     16);
        cp16(Bs[buf] + so1, bsrc + k0 + 8, 16);
    };

    const int KT = EDIM / BK;       // 32
    load_stage(0, 0);      cp_commit();
    load_stage(1, BK);     cp_commit();
    for (int kt = 0; kt < KT; kt++) {
        cp_wait1();                  // stage kt resident (kt+1 may be pending)
        __syncthreads();             // visibility + prior-stage consumers done
        if (kt + 2 < KT) load_stage((kt + 2) % NSTG, (kt + 2) * BK);
        cp_commit();                 // uniform group count (empty ok)
        mma_stage(As[kt % NSTG], Bs[kt % NSTG], wm, wn, lane, acc);
    }

    // epilogue: +b1, exact GELU, store hid (fp16)
#pragma unroll
    for (int nj = 0; nj < 4; nj++) {
        int n = n0 + wn + nj * 8 + qk * 2;
        float b1a = b1[(size_t)e * HDIM + n];
        float b1b = b1[(size_t)e * HDIM + n + 1];
#pragma unroll
        for (int mi = 0; mi < 4; mi++) {
#pragma unroll
            for (int h = 0; h < 2; h++) {
                int m = m0 + wm + mi * 16 + gi + h * 8;
                if (m >= cnt) continue;
                float vx = gelu_exact(acc[mi][nj][h * 2 + 0] + b1a);
                float vy = gelu_exact(acc[mi][nj][h * 2 + 1] + b1b);
                *(half2*)(g_hid + ((size_t)e * CAP + m) * HDIM + n) =
                    __floats2half2_rn(vx, vy);
            }
        }
    }
}

// K3: out[tok] += w * (hid @ W2T[e]^T + b2[e])
__global__ __launch_bounds__(256, 2) void k_ffn2(const float* __restrict__ b2,
                                                 float* __restrict__ out) {
    int e   = blockIdx.z;
    int cnt = g_cnt[e];
    int m0  = blockIdx.y * 128;
    if (m0 >= cnt) return;
    int n0  = blockIdx.x * 128;

    __shared__ __align__(16) __half As[NSTG][128 * BK];
    __shared__ __align__(16) __half Bs[NSTG][128 * BK];
    __shared__ int   toks[128];
    __shared__ float wts[128];

    int tid = threadIdx.x;
    if (tid < 128) {
        int m = m0 + tid;
        bool v = (m < cnt);
        toks[tid] = v ? g_tok[e * CAP + m] : -1;
        wts[tid]  = v ? g_wgt[e * CAP + m] : 0.f;
    }
    __syncthreads();

    int mlim = cnt - m0;
    int lane = tid & 31, warp = tid >> 5;
    int gi = lane >> 2, qk = lane & 3;
    int wm = (warp >> 2) * 64, wn = (warp & 3) * 32;

    int lr = tid >> 1, c0 = (tid & 1) * 2, lc = (tid & 1) * 16;
    bool mval = (lr < mlim);
    int abytes = mval ? 16 : 0;
    const __half* asrc = g_hid + ((size_t)e * CAP + m0 + (mval ? lr : 0)) * HDIM + lc;
    const __half* bsrc = g_w2t + ((size_t)e * EDIM + n0 + lr) * HDIM + lc;
    unsigned so0 = sw_off(lr, c0), so1 = sw_off(lr, c0 + 1);

    float acc[4][4][4];
#pragma unroll
    for (int i = 0; i < 4; i++)
#pragma unroll
        for (int j = 0; j < 4; j++)
#pragma unroll
            for (int r = 0; r < 4; r++) acc[i][j][r] = 0.f;

    auto load_stage = [&](int buf, int k0) {
        cp16(As[buf] + so0, asrc + k0,     abytes);
        cp16(As[buf] + so1, asrc + k0 + 8, abytes);
        cp16(Bs[buf] + so0, bsrc + k0,     16);
        cp16(Bs[buf] + so1, bsrc + k0 + 8, 16);
    };

    const int KT = HDIM / BK;       // 128
    load_stage(0, 0);      cp_commit();
    load_stage(1, BK);     cp_commit();
    for (int kt = 0; kt < KT; kt++) {
        cp_wait1();
        __syncthreads();
        if (kt + 2 < KT) load_stage((kt + 2) % NSTG, (kt + 2) * BK);
        cp_commit();
        mma_stage(As[kt % NSTG], Bs[kt % NSTG], wm, wn, lane, acc);
    }

#pragma unroll
    for (int nj = 0; nj < 4; nj++) {
        int n = n0 + wn + nj * 8 + qk * 2;
        float b2a = b2[(size_t)e * EDIM + n];
        float b2b = b2[(size_t)e * EDIM + n + 1];
#pragma unroll
        for (int mi = 0; mi < 4; mi++) {
#pragma unroll
            for (int h = 0; h < 2; h++) {
                int ml = wm + mi * 16 + gi + h * 8;
                int tok = toks[ml];
                if (tok < 0) continue;
                float w = wts[ml];
                float* op = out + (size_t)tok * EDIM + n;
                atomicAdd(op + 0, w * (acc[mi][nj][h * 2 + 0] + b2a));
                atomicAdd(op + 1, w * (acc[mi][nj][h * 2 + 1] + b2b));
            }
        }
    }
}

// ---------------------------------------------------------------------------
extern "C" void kernel_launch(void* const* d_in, const int* in_sizes, int n_in,
                              void* d_out, int out_size) {
    const float* x  = (const float*)d_in[0];
    const float* Wr = (const float*)d_in[1];
    const float* br = (const float*)d_in[2];
    const float* W1 = (const float*)d_in[3];
    const float* b1 = (const float*)d_in[4];
    const float* W2 = (const float*)d_in[5];
    const float* b2 = (const float*)d_in[6];
    float* out = (float*)d_out;
    (void)in_sizes; (void)n_in; (void)out_size;

    k_zero<<<4096, 256>>>(out);
    k_convx<<<(TNUM * EDIM / 2 + 255) / 256, 256>>>(x);
    {   dim3 g(HDIM / 32, EDIM / 32, NEXP);
        k_convW<0><<<g, 256>>>(W1); }
    {   dim3 g(EDIM / 32, HDIM / 32, NEXP);
        k_convW<1><<<g, 256>>>(W2); }
    k_router<<<TNUM / 8, 256>>>(x, Wr, br);
    dim3 g1(HDIM / 128, CAP / 128, NEXP);
    k_ffn1<<<g1, 256>>>(b1);
    dim3 g2(EDIM / 128, CAP / 128, NEXP);
    k_ffn2<<<g2, 256>>>(b2, out);
}